// round 2
// baseline (speedup 1.0000x reference)
#include <cuda_runtime.h>
#include <cuda_bf16.h>
#include <cfloat>

// Problem constants (StyleCodebook: B=16, N=4096, D=256, K=512)
static constexpr int TOKENS = 16 * 4096;   // 65536
static constexpr int D      = 256;
static constexpr int K      = 512;

// Tiling for the fused distance+argmin kernel
static constexpr int BM = 64;    // tokens per CTA
static constexpr int BN = 128;   // codes per chunk
static constexpr int NCHUNK = K / BN;  // 4
static constexpr int TM = 4;     // tokens per thread
static constexpr int TN = 8;     // codes per thread
// 16x16 thread grid = 256 threads

// smem layout (dynamic): zs[D][BM] | es[D][BN] | esq[K]
static constexpr size_t ZS_FLOATS  = (size_t)D * BM;          // 16384
static constexpr size_t ES_FLOATS  = (size_t)D * BN;          // 32768
static constexpr size_t SMEM_BYTES = (ZS_FLOATS + ES_FLOATS + K) * sizeof(float); // 198656

// Scratch (device globals; no allocation allowed)
__device__ int   g_indices[TOKENS];
__device__ float g_partial[TOKENS];
__device__ float g_esq[K];

// ---------------------------------------------------------------------------
// Kernel 0: codebook row squared norms
// ---------------------------------------------------------------------------
__global__ void esq_kernel(const float* __restrict__ cb) {
    int k = blockIdx.x;        // one block per code
    int d = threadIdx.x;       // D threads
    float v = cb[(size_t)k * D + d];
    float s = v * v;
    #pragma unroll
    for (int o = 16; o > 0; o >>= 1) s += __shfl_down_sync(0xffffffffu, s, o);
    __shared__ float ws[8];
    if ((d & 31) == 0) ws[d >> 5] = s;
    __syncthreads();
    if (d == 0) {
        float tot = 0.f;
        #pragma unroll
        for (int w = 0; w < 8; ++w) tot += ws[w];
        g_esq[k] = tot;
    }
}

// ---------------------------------------------------------------------------
// Kernel 1: fused z @ cb^T with running argmin per token
// dist(k) = ||e_k||^2 - 2 * z.e_k   (z^2 term is constant per token)
// ---------------------------------------------------------------------------
__global__ void __launch_bounds__(256, 1)
argmin_kernel(const float* __restrict__ z, const float* __restrict__ cb) {
    extern __shared__ float smem[];
    float* zs    = smem;                         // [D][BM] transposed
    float* es    = smem + ZS_FLOATS;             // [D][BN] transposed
    float* esq_s = smem + ZS_FLOATS + ES_FLOATS; // [K]

    const int tid = threadIdx.x;
    const int tx  = tid & 15;
    const int ty  = tid >> 4;
    const int m0  = blockIdx.x * BM;

    // Load z tile transposed: zs[d][m]
    for (int i = tid; i < BM * (D / 4); i += 256) {
        int m  = i & (BM - 1);
        int d4 = i >> 6;                 // 0..63
        float4 v = *reinterpret_cast<const float4*>(z + (size_t)(m0 + m) * D + d4 * 4);
        zs[(d4 * 4 + 0) * BM + m] = v.x;
        zs[(d4 * 4 + 1) * BM + m] = v.y;
        zs[(d4 * 4 + 2) * BM + m] = v.z;
        zs[(d4 * 4 + 3) * BM + m] = v.w;
    }
    for (int i = tid; i < K; i += 256) esq_s[i] = g_esq[i];

    float bestD[TM];
    int   bestI[TM];
    #pragma unroll
    for (int mm = 0; mm < TM; ++mm) { bestD[mm] = FLT_MAX; bestI[mm] = 0; }

    for (int ch = 0; ch < NCHUNK; ++ch) {
        __syncthreads();  // prev compute done (and, 1st iter, zs/esq stores done)
        const int c0 = ch * BN;
        // Load codebook chunk transposed: es[d][c]
        for (int i = tid; i < BN * (D / 4); i += 256) {
            int c  = i & (BN - 1);
            int d4 = i >> 7;             // 0..63
            float4 v = *reinterpret_cast<const float4*>(cb + (size_t)(c0 + c) * D + d4 * 4);
            es[(d4 * 4 + 0) * BN + c] = v.x;
            es[(d4 * 4 + 1) * BN + c] = v.y;
            es[(d4 * 4 + 2) * BN + c] = v.z;
            es[(d4 * 4 + 3) * BN + c] = v.w;
        }
        __syncthreads();

        float acc[TM][TN];
        #pragma unroll
        for (int mm = 0; mm < TM; ++mm)
            #pragma unroll
            for (int nn = 0; nn < TN; ++nn) acc[mm][nn] = 0.f;

        #pragma unroll 8
        for (int k = 0; k < D; ++k) {
            const float4 zv = *reinterpret_cast<const float4*>(&zs[k * BM + ty * TM]);
            const float4 ea = *reinterpret_cast<const float4*>(&es[k * BN + tx * TN]);
            const float4 eb = *reinterpret_cast<const float4*>(&es[k * BN + tx * TN + 4]);
            const float zr[TM] = {zv.x, zv.y, zv.z, zv.w};
            const float er[TN] = {ea.x, ea.y, ea.z, ea.w, eb.x, eb.y, eb.z, eb.w};
            #pragma unroll
            for (int mm = 0; mm < TM; ++mm)
                #pragma unroll
                for (int nn = 0; nn < TN; ++nn)
                    acc[mm][nn] += zr[mm] * er[nn];
        }

        // Running argmin. Codes of this thread are ascending across (ch, nn),
        // so strict '<' keeps the earliest index on exact ties (jnp.argmin).
        #pragma unroll
        for (int mm = 0; mm < TM; ++mm) {
            #pragma unroll
            for (int nn = 0; nn < TN; ++nn) {
                int code = c0 + tx * TN + nn;
                float dist = esq_s[code] - 2.0f * acc[mm][nn];
                if (dist < bestD[mm]) { bestD[mm] = dist; bestI[mm] = code; }
            }
        }
    }

    // Cross-thread reduction over tx (16 candidates per token), reusing es.
    __syncthreads();
    float* rd = es;                         // [16][BM]
    int*   ri = (int*)(es + 16 * BM);       // [16][BM]
    #pragma unroll
    for (int mm = 0; mm < TM; ++mm) {
        int m = ty * TM + mm;
        rd[tx * BM + m] = bestD[mm];
        ri[tx * BM + m] = bestI[mm];
    }
    __syncthreads();
    if (tid < BM) {
        float bd = rd[tid];
        int   bi = ri[tid];
        #pragma unroll
        for (int t = 1; t < 16; ++t) {
            float d2 = rd[t * BM + tid];
            int   i2 = ri[t * BM + tid];
            if (d2 < bd || (d2 == bd && i2 < bi)) { bd = d2; bi = i2; }
        }
        g_indices[m0 + tid] = bi;
    }
}

// ---------------------------------------------------------------------------
// Kernel 2: gather codebook rows, write quantized & indices, per-token loss
// mask read as 4-byte words: nonzero == true (covers int32 0/1 and f32 0/1)
// ---------------------------------------------------------------------------
__global__ void gather_kernel(const float* __restrict__ z,
                              const unsigned* __restrict__ mask,
                              const float* __restrict__ cb,
                              float* __restrict__ outQ,
                              float* __restrict__ outI) {
    const int t = blockIdx.x;
    const int d = threadIdx.x;          // 256 threads = D
    const int idx = g_indices[t];
    const unsigned mw = mask[t];

    const float zv = z[(size_t)t * D + d];
    const float ev = cb[(size_t)idx * D + d];
    outQ[(size_t)t * D + d] = mw ? ev : 0.0f;

    float diff = ev - zv;
    float s = diff * diff;
    #pragma unroll
    for (int o = 16; o > 0; o >>= 1) s += __shfl_down_sync(0xffffffffu, s, o);
    __shared__ float ws[8];
    if ((d & 31) == 0) ws[d >> 5] = s;
    __syncthreads();
    if (d == 0) {
        float tot = 0.f;
        #pragma unroll
        for (int w = 0; w < 8; ++w) tot += ws[w];
        g_partial[t] = tot;
        outI[t] = mw ? (float)idx : -1.0f;
    }
}

// ---------------------------------------------------------------------------
// Kernel 3: deterministic loss reduction (fixed order, no float atomics)
// ---------------------------------------------------------------------------
__global__ void loss_kernel(float* __restrict__ outL) {
    __shared__ float sm[256];
    const int tid = threadIdx.x;
    float a = 0.f;
    for (int i = tid; i < TOKENS; i += 256) a += g_partial[i];
    sm[tid] = a;
    __syncthreads();
    #pragma unroll
    for (int s = 128; s > 0; s >>= 1) {
        if (tid < s) sm[tid] += sm[tid + s];
        __syncthreads();
    }
    if (tid == 0)
        outL[0] = 0.25f * sm[0] / (float)((size_t)TOKENS * D);
}

// ---------------------------------------------------------------------------
extern "C" void kernel_launch(void* const* d_in, const int* in_sizes, int n_in,
                              void* d_out, int out_size) {
    const float*    z    = (const float*)d_in[0];
    const unsigned* mask = (const unsigned*)d_in[1];
    const float*    cb   = (const float*)d_in[2];

    float* out  = (float*)d_out;
    float* outQ = out;
    float* outI = out + (size_t)TOKENS * D;
    float* outL = outI + TOKENS;

    cudaFuncSetAttribute(argmin_kernel,
                         cudaFuncAttributeMaxDynamicSharedMemorySize,
                         (int)SMEM_BYTES);

    esq_kernel<<<K, D>>>(cb);
    argmin_kernel<<<TOKENS / BM, 256, SMEM_BYTES>>>(z, cb);
    gather_kernel<<<TOKENS, D>>>(z, mask, cb, outQ, outI);
    loss_kernel<<<1, 256>>>(outL);
}